// round 11
// baseline (speedup 1.0000x reference)
#include <cuda_runtime.h>
#include <cuda_fp16.h>

// Problem constants
#define NNODE   10000
#define NEDGE   160000
#define FIN     3703
#define KPAD    3712     // FIN padded to multiple of 16
#define DMODEL  256
#define NHEAD   32
#define DK      16
#define QKV     512      // NHEAD*DK
#define QKV3    1536     // fused Q|K|V width
#define NLAYER  7

// GEMM tiling (fp16 3-term, 3-stage cp.async pipeline)
#define BM 128
#define BN 128
#define SROWH 24                   // 16 halves + 8 pad (48B rows, LDSM conflict-free)
#define TILE_H (128*SROWH)         // 3072 halves per tile
#define STAGE_H (4*TILE_H)         // Ah | Al | Bh | Bl = 24KB
#define NSTAGE 3
#define GEMM_SMEM_BYTES (NSTAGE*STAGE_H*2)   // 73728
#define WSCALE 32.0f
#define WINV   0.03125f

#define SQ1 (QKV*DMODEL)           // 131072 (one layer of Wq)
#define SQT (NLAYER*SQ1)           // 917504
#define SOT (NLAYER*DMODEL*QKV)    // 917504
#define SMT (NLAYER*DMODEL*DMODEL) // 458752
#define WTOT (3*SQT + SOT + SMT)

// ---------------- device scratch ----------------
__device__ __half g_xh [NNODE * KPAD];
__device__ __half g_xl [NNODE * KPAD];
__device__ __half g_Weh[DMODEL * KPAD];
__device__ __half g_Wel[DMODEL * KPAD];
__device__ __half g_Wfh[NLAYER * QKV3 * DMODEL];   // fused Wq|Wk|Wv (x32)
__device__ __half g_Wfl[NLAYER * QKV3 * DMODEL];
__device__ __half g_Woh[SOT];
__device__ __half g_Wol[SOT];
__device__ __half g_Wmh[SMT];
__device__ __half g_Wml[SMT];

__device__ float  g_h  [NNODE * DMODEL];
__device__ __half g_hh [NNODE * DMODEL];
__device__ __half g_hl [NNODE * DMODEL];
__device__ float  g_t0 [NNODE * DMODEL];
__device__ float  g_t1 [NNODE * DMODEL];
__device__ __half g_t1h[NNODE * DMODEL];
__device__ __half g_t1l[NNODE * DMODEL];
__device__ float  g_QKV[NNODE * QKV3];
__device__ __half g_ath[NNODE * QKV];
__device__ __half g_atl[NNODE * QKV];

__device__ int g_cnt [NNODE];
__device__ int g_off [NNODE + 1];
__device__ int g_cur [NNODE];
__device__ int g_esrc[NEDGE];
__device__ int g_is64;

// ---------------- fp16 two-term split ----------------
__device__ __forceinline__ void splith(float x, __half& hi, __half& lo) {
    hi = __float2half_rn(x);
    lo = __float2half_rn(x - __half2float(hi));
}

// ---------------- f32x2 packed helpers (sm_103a FFMA2) ----------------
__device__ __forceinline__ unsigned long long pack2(float lo, float hi) {
    unsigned long long r;
    asm("mov.b64 %0, {%1, %2};" : "=l"(r) : "f"(lo), "f"(hi));
    return r;
}
__device__ __forceinline__ void unpack2(unsigned long long v, float& lo, float& hi) {
    asm("mov.b64 {%0, %1}, %2;" : "=f"(lo), "=f"(hi) : "l"(v));
}
__device__ __forceinline__ void fma2(unsigned long long& d,
                                     unsigned long long a, unsigned long long b) {
    asm("fma.rn.f32x2 %0, %1, %2, %0;" : "+l"(d) : "l"(a), "l"(b));
}
__device__ __forceinline__ unsigned long long add2(unsigned long long a,
                                                   unsigned long long b) {
    unsigned long long r;
    asm("add.rn.f32x2 %0, %1, %2;" : "=l"(r) : "l"(a), "l"(b));
    return r;
}

// ---------------- split kernels ----------------
__global__ void split_pad_kernel(const float* __restrict__ src,
                                 __half* __restrict__ hi, __half* __restrict__ lo,
                                 int cols, int colspad, float scale) {
    int row = blockIdx.x;
    const float* s = src + (size_t)row * cols;
    __half* ph = hi + (size_t)row * colspad;
    __half* pl = lo + (size_t)row * colspad;
    for (int c = threadIdx.x; c < cols; c += blockDim.x) {
        __half h, l;
        splith(s[c] * scale, h, l);
        ph[c] = h; pl[c] = l;
    }
}

__global__ void splitw_kernel(const float* __restrict__ Wq, const float* __restrict__ Wk,
                              const float* __restrict__ Wv, const float* __restrict__ Wo,
                              const float* __restrict__ Wm) {
    int idx = blockIdx.x * blockDim.x + threadIdx.x;
    if (idx >= WTOT) return;
    float v; __half *dh, *dl;
    if (idx < SQT) {
        int l = idx / SQ1, r = idx % SQ1;
        v = Wq[idx]; int d = l * (3 * SQ1) + r;
        dh = g_Wfh + d; dl = g_Wfl + d;
    } else if (idx < 2 * SQT) {
        int i2 = idx - SQT;
        int l = i2 / SQ1, r = i2 % SQ1;
        v = Wk[i2]; int d = l * (3 * SQ1) + SQ1 + r;
        dh = g_Wfh + d; dl = g_Wfl + d;
    } else if (idx < 3 * SQT) {
        int i2 = idx - 2 * SQT;
        int l = i2 / SQ1, r = i2 % SQ1;
        v = Wv[i2]; int d = l * (3 * SQ1) + 2 * SQ1 + r;
        dh = g_Wfh + d; dl = g_Wfl + d;
    } else if (idx < 3 * SQT + SOT) {
        int i2 = idx - 3 * SQT;
        v = Wo[i2]; dh = g_Woh + i2; dl = g_Wol + i2;
    } else {
        int i2 = idx - 3 * SQT - SOT;
        v = Wm[i2]; dh = g_Wmh + i2; dl = g_Wml + i2;
    }
    __half h, l;
    splith(v * WSCALE, h, l);
    *dh = h; *dl = l;
}

// ---------------- edge index dtype detection + CSR ----------------
__global__ void detect_kernel(const unsigned int* __restrict__ w) {
    if (threadIdx.x == 0 && blockIdx.x == 0) {
        int is64 = 1;
        for (int i = 1; i < 128; i += 2)
            if (w[i] != 0u) { is64 = 0; break; }
        g_is64 = is64;
    }
}

__device__ __forceinline__ int read_edge(const void* eidx, int pos) {
    if (g_is64) return (int)(((const long long*)eidx)[pos]);
    return ((const int*)eidx)[pos];
}

__global__ void zero_cnt_kernel() {
    int i = blockIdx.x * blockDim.x + threadIdx.x;
    if (i < NNODE) g_cnt[i] = 0;
}

__global__ void hist_kernel(const void* __restrict__ eidx) {
    int e = blockIdx.x * blockDim.x + threadIdx.x;
    if (e >= NEDGE) return;
    atomicAdd(&g_cnt[read_edge(eidx, NEDGE + e)], 1);
}

__global__ void scan_kernel() {
    __shared__ int ss[1024];
    int t = threadIdx.x;
    const int CH = (NNODE + 1023) / 1024;
    int b = t * CH;
    int e = b + CH; if (e > NNODE) e = NNODE;
    int s = 0;
    for (int i = b; i < e; i++) s += g_cnt[i];
    ss[t] = s;
    __syncthreads();
    for (int o = 1; o < 1024; o <<= 1) {
        int v = (t >= o) ? ss[t - o] : 0;
        __syncthreads();
        ss[t] += v;
        __syncthreads();
    }
    int base = ss[t] - s;
    for (int i = b; i < e; i++) {
        g_off[i] = base;
        g_cur[i] = base;
        base += g_cnt[i];
    }
    if (t == 1023) g_off[NNODE] = ss[1023];
}

__global__ void scatter_kernel(const void* __restrict__ eidx) {
    int e = blockIdx.x * blockDim.x + threadIdx.x;
    if (e >= NEDGE) return;
    int d = read_edge(eidx, NEDGE + e);
    int s = read_edge(eidx, e);
    g_esrc[atomicAdd(&g_cur[d], 1)] = s;
}

// ---------------- fp16 mma + ldmatrix + cp.async helpers ----------------
__device__ __forceinline__ void mma16(float* c,
                                      unsigned a0, unsigned a1, unsigned a2, unsigned a3,
                                      unsigned b0, unsigned b1) {
    asm volatile(
        "mma.sync.aligned.m16n8k16.row.col.f32.f16.f16.f32 "
        "{%0,%1,%2,%3}, {%4,%5,%6,%7}, {%8,%9}, {%0,%1,%2,%3};\n"
        : "+f"(c[0]), "+f"(c[1]), "+f"(c[2]), "+f"(c[3])
        : "r"(a0), "r"(a1), "r"(a2), "r"(a3), "r"(b0), "r"(b1));
}

__device__ __forceinline__ void ldsm4(unsigned& r0, unsigned& r1,
                                      unsigned& r2, unsigned& r3, unsigned addr) {
    asm volatile(
        "ldmatrix.sync.aligned.m8n8.x4.shared.b16 {%0,%1,%2,%3}, [%4];\n"
        : "=r"(r0), "=r"(r1), "=r"(r2), "=r"(r3) : "r"(addr));
}

__device__ __forceinline__ void cpa16(unsigned dst, const __half* src) {
    asm volatile("cp.async.ca.shared.global [%0], [%1], 16;\n"
                 :: "r"(dst), "l"(src));
}

// ---------------- GEMM: C = addend + bias + (A @ B^T)/32  (3xFP16) --------
// BM=128, 3-stage cp.async pipeline; all loads clamped in-bounds; invalid
// rows dropped in epilogue.
__global__ __launch_bounds__(256, 2)
void gemm3h(const __half* __restrict__ Ah, const __half* __restrict__ Al,
            const __half* __restrict__ Bh, const __half* __restrict__ Bl,
            const float* __restrict__ bias, const float* __restrict__ addend,
            float* __restrict__ C, __half* __restrict__ Ch, __half* __restrict__ Cl,
            int M, int Nn, int K)
{
    extern __shared__ __align__(16) __half smem[];   // NSTAGE * STAGE_H

    const int tid = threadIdx.x;
    const int m0 = blockIdx.y * BM;
    const int n0 = blockIdx.x * BN;
    const int lane = tid & 31, wid = tid >> 5;
    const int wm = wid & 1, wn = wid >> 1;

    const int nkt = K >> 4;

    float acc[4][4][4] = {};

    const int lr = tid >> 1;            // row 0..127
    const int lc = (tid & 1) * 8;       // half-col 0 or 8
    const int mA = (m0 + lr < M) ? (m0 + lr) : (M - 1);
    const int nB = n0 + lr;             // Nn multiple of 128

    const int a_row = ((lane >> 3) & 1) * 8 + (lane & 7);
    const int a_col = ((lane >> 4) & 1) * 8;
    const unsigned aoffB = (unsigned)((a_row * SROWH + a_col) * 2);
    const int b_row = ((lane >> 4) & 1) * 8 + (lane & 7);
    const int b_col = ((lane >> 3) & 1) * 8;
    const unsigned boffB = (unsigned)((b_row * SROWH + b_col) * 2);

    const unsigned sb0 = (unsigned)__cvta_generic_to_shared(smem);
    const unsigned dstOff = (unsigned)((lr * SROWH + lc) * 2);   // bytes in a tile

    // issue one stage's 4 cp.async copies (Ah|Al|Bh|Bl) + commit
#define ISSUE(t_) do {                                                         \
        const int _k16 = (t_) << 4;                                           \
        const unsigned _s = sb0 + (unsigned)(((t_) % NSTAGE) * STAGE_H * 2);   \
        cpa16(_s + dstOff,                          Ah + (size_t)mA * K + _k16 + lc); \
        cpa16(_s + (unsigned)(TILE_H * 2) + dstOff, Al + (size_t)mA * K + _k16 + lc); \
        cpa16(_s + (unsigned)(2 * TILE_H * 2) + dstOff, Bh + (size_t)nB * K + _k16 + lc); \
        cpa16(_s + (unsigned)(3 * TILE_H * 2) + dstOff, Bl + (size_t)nB * K + _k16 + lc); \
        asm volatile("cp.async.commit_group;\n");                              \
    } while (0)

    ISSUE(0);
    if (nkt > 1) ISSUE(1);

    for (int t = 0; t < nkt; t++) {
        // groups committed so far = min(t+2, nkt); need group t complete
        if (t + 1 < nkt) asm volatile("cp.async.wait_group 1;\n");
        else             asm volatile("cp.async.wait_group 0;\n");
        __syncthreads();

        const unsigned sb = sb0 + (unsigned)((t % NSTAGE) * STAGE_H * 2);

        unsigned bh0[4], bh1[4], bl0[4], bl1[4];
#pragma unroll
        for (int jp = 0; jp < 2; jp++) {
            unsigned bd = sb + (unsigned)((2 * TILE_H + (wn * 32 + jp * 16) * SROWH) * 2) + boffB;
            ldsm4(bh0[2 * jp], bh1[2 * jp], bh0[2 * jp + 1], bh1[2 * jp + 1], bd);
            ldsm4(bl0[2 * jp], bl1[2 * jp], bl0[2 * jp + 1], bl1[2 * jp + 1],
                  bd + (unsigned)(TILE_H * 2));
        }
#pragma unroll
        for (int i = 0; i < 4; i++) {
            unsigned ad = sb + (unsigned)(((wm * 64 + i * 16) * SROWH) * 2) + aoffB;
            unsigned ah0, ah1, ah2, ah3, al0, al1, al2, al3;
            ldsm4(ah0, ah1, ah2, ah3, ad);
            ldsm4(al0, al1, al2, al3, ad + (unsigned)(TILE_H * 2));
#pragma unroll
            for (int j = 0; j < 4; j++) {
                mma16(acc[i][j], ah0, ah1, ah2, ah3, bh0[j], bh1[j]);
                mma16(acc[i][j], al0, al1, al2, al3, bh0[j], bh1[j]);
                mma16(acc[i][j], ah0, ah1, ah2, ah3, bl0[j], bl1[j]);
            }
        }

        // refill the stage freed at iteration t-1 (fenced by this iter's sync)
        if (t + 2 < nkt) ISSUE(t + 2);
        __syncthreads();
    }
#undef ISSUE

    // epilogue: rescale by 1/32 (weights were pre-scaled x32)
#pragma unroll
    for (int i = 0; i < 4; i++) {
        int mrow = m0 + wm * 64 + i * 16 + (lane >> 2);
#pragma unroll
        for (int j = 0; j < 4; j++) {
            int ncol = n0 + wn * 32 + j * 8 + (lane & 3) * 2;
            float bv0 = 0.f, bv1 = 0.f;
            if (bias) { bv0 = bias[ncol]; bv1 = bias[ncol + 1]; }
#pragma unroll
            for (int r = 0; r < 2; r++) {
                int mr = mrow + r * 8;
                if (mr >= M) continue;
                size_t idx = (size_t)mr * Nn + ncol;
                float v0 = acc[i][j][r * 2 + 0] * WINV + bv0;
                float v1 = acc[i][j][r * 2 + 1] * WINV + bv1;
                if (addend) { v0 += addend[idx]; v1 += addend[idx + 1]; }
                C[idx]     = v0;
                C[idx + 1] = v1;
                if (Ch) {
                    __half h0, l0, h1, l1;
                    splith(v0, h0, l0);
                    splith(v1, h1, l1);
                    Ch[idx] = h0;      Cl[idx] = l0;
                    Ch[idx + 1] = h1;  Cl[idx + 1] = l1;
                }
            }
        }
    }
}

// ---------------- LayerNorm (warp per row) with optional split outputs ----
__global__ __launch_bounds__(256)
void ln_kernel(const float* __restrict__ X, const float* __restrict__ gamma,
               const float* __restrict__ beta, float* __restrict__ Y,
               __half* __restrict__ Yh, __half* __restrict__ Yl)
{
    int idx = blockIdx.x * blockDim.x + threadIdx.x;
    int row = idx >> 5;
    int lane = idx & 31;
    if (row >= NNODE) return;

    const float4* xp = (const float4*)(X + (size_t)row * DMODEL);
    float4 v0 = xp[lane];
    float4 v1 = xp[lane + 32];

    float s = v0.x + v0.y + v0.z + v0.w + v1.x + v1.y + v1.z + v1.w;
#pragma unroll
    for (int o = 16; o; o >>= 1) s += __shfl_xor_sync(0xffffffffu, s, o);
    float mean = s * (1.f / 256.f);

    float d, q = 0.f;
    d = v0.x - mean; q += d * d;  d = v0.y - mean; q += d * d;
    d = v0.z - mean; q += d * d;  d = v0.w - mean; q += d * d;
    d = v1.x - mean; q += d * d;  d = v1.y - mean; q += d * d;
    d = v1.z - mean; q += d * d;  d = v1.w - mean; q += d * d;
#pragma unroll
    for (int o = 16; o; o >>= 1) q += __shfl_xor_sync(0xffffffffu, q, o);
    float inv = rsqrtf(q * (1.f / 256.f) + 1e-5f);

    const float4* gp = (const float4*)gamma;
    const float4* bp = (const float4*)beta;
    float4 g0 = gp[lane], g1 = gp[lane + 32];
    float4 b0 = bp[lane], b1 = bp[lane + 32];

    float o0[4], o1[4];
    o0[0] = (v0.x - mean) * inv * g0.x + b0.x;
    o0[1] = (v0.y - mean) * inv * g0.y + b0.y;
    o0[2] = (v0.z - mean) * inv * g0.z + b0.z;
    o0[3] = (v0.w - mean) * inv * g0.w + b0.w;
    o1[0] = (v1.x - mean) * inv * g1.x + b1.x;
    o1[1] = (v1.y - mean) * inv * g1.y + b1.y;
    o1[2] = (v1.z - mean) * inv * g1.z + b1.z;
    o1[3] = (v1.w - mean) * inv * g1.w + b1.w;

    float4* yp = (float4*)(Y + (size_t)row * DMODEL);
    yp[lane]      = make_float4(o0[0], o0[1], o0[2], o0[3]);
    yp[lane + 32] = make_float4(o1[0], o1[1], o1[2], o1[3]);

    if (Yh) {
        __half hbuf0[4], lbuf0[4], hbuf1[4], lbuf1[4];
#pragma unroll
        for (int k = 0; k < 4; k++) {
            splith(o0[k], hbuf0[k], lbuf0[k]);
            splith(o1[k], hbuf1[k], lbuf1[k]);
        }
        uint2* hp = (uint2*)(Yh + (size_t)row * DMODEL);
        uint2* lp = (uint2*)(Yl + (size_t)row * DMODEL);
        hp[lane]      = *(uint2*)hbuf0;
        hp[lane + 32] = *(uint2*)hbuf1;
        lp[lane]      = *(uint2*)lbuf0;
        lp[lane + 32] = *(uint2*)lbuf1;
    }
}

// ---------------- edge attention: warp/node, f32x2, Q packed in smem -----
__global__ __launch_bounds__(128)
void attn_kernel(const float* __restrict__ QKVm,
                 __half* __restrict__ Omh, __half* __restrict__ Oml)
{
    __shared__ unsigned long long Qd[4][512];     // (qa/4, qa/4) per (h*16+a)
    __shared__ float KVs[4][2][1024];             // double-buffered K|V

    const int gwarp = (blockIdx.x * blockDim.x + threadIdx.x) >> 5;
    const int lane  = threadIdx.x & 31;
    const int winb  = threadIdx.x >> 5;
    if (gwarp >= NNODE) return;

    const int i = gwarp;
    const int a = lane >> 1;
    const int half = lane & 1;
    const int half2 = half * 2;

    {
        const float4* qg = (const float4*)(QKVm + (size_t)i * QKV3);
#pragma unroll
        for (int v = 0; v < 4; v++) {
            float4 q = qg[lane + 32 * v];
            int e = (lane + 32 * v) * 4;
            ulonglong2* d = (ulonglong2*)&Qd[winb][e];
            float x0 = q.x * 0.25f, x1 = q.y * 0.25f;
            float x2 = q.z * 0.25f, x3 = q.w * 0.25f;
            d[0] = make_ulonglong2(pack2(x0, x0), pack2(x1, x1));
            d[1] = make_ulonglong2(pack2(x2, x2), pack2(x3, x3));
        }
    }

    unsigned long long partial2[32];
#pragma unroll
    for (int h = 0; h < 32; h++) partial2[h] = 0ull;

    const int e0 = g_off[i];
    const int e1 = g_off[i + 1];

    float4 kr[4], vr[4];
    if (e0 < e1) {
        const float4* kg = (const float4*)(QKVm + (size_t)g_esrc[e0] * QKV3 + QKV);
        const float4* vg = kg + 128;
#pragma unroll
        for (int v = 0; v < 4; v++) { kr[v] = kg[lane + 32 * v]; vr[v] = vg[lane + 32 * v]; }
        float4* kd = (float4*)&KVs[winb][0][0];
        float4* vd = kd + 128;
#pragma unroll
        for (int v = 0; v < 4; v++) { kd[lane + 32 * v] = kr[v]; vd[lane + 32 * v] = vr[v]; }
    }
    __syncwarp();

    int cur = 0;
    for (int e = e0; e < e1; e++) {
        if (e + 1 < e1) {
            const float4* kg = (const float4*)(QKVm + (size_t)g_esrc[e + 1] * QKV3 + QKV);
            const float4* vg = kg + 128;
#pragma unroll
            for (int v = 0; v < 4; v++) { kr[v] = kg[lane + 32 * v]; vr[v] = vg[lane + 32 * v]; }
        }

        const ulonglong2* Ks2 = (const ulonglong2*)&KVs[winb][cur][0];
        const ulonglong2* Vs2 = Ks2 + 128;

        unsigned long long acc2[8] = {0ull,0ull,0ull,0ull,0ull,0ull,0ull,0ull};
#pragma unroll
        for (int hh = 0; hh < 32; hh += 2) {
            unsigned long long q0 = Qd[winb][hh * 16 + a];
            unsigned long long q1 = Qd[winb][(hh + 1) * 16 + a];
            ulonglong2 kA0 = Ks2[hh * 4 + half2];
            ulonglong2 kB0 = Ks2[hh * 4 + half2 + 1];
            ulonglong2 kA1 = Ks2[(hh + 1) * 4 + half2];
            ulonglong2 kB1 = Ks2[(hh + 1) * 4 + half2 + 1];
            fma2(acc2[0], q0, kA0.x); fma2(acc2[1], q0, kA0.y);
            fma2(acc2[2], q0, kB0.x); fma2(acc2[3], q0, kB0.y);
            fma2(acc2[4], q1, kA1.x); fma2(acc2[5], q1, kA1.y);
            fma2(acc2[6], q1, kB1.x); fma2(acc2[7], q1, kB1.y);
        }
        acc2[0] = add2(acc2[0], acc2[4]);
        acc2[1] = add2(acc2[1], acc2[5]);
        acc2[2] = add2(acc2[2], acc2[6]);
        acc2[3] = add2(acc2[3], acc2[7]);

        float a8[8];
        unpack2(acc2[0], a8[0], a8[1]);
        unpack2(acc2[1], a8[2], a8[3]);
        unpack2(acc2[2], a8[4], a8[5]);
        unpack2(acc2[3], a8[6], a8[7]);
        float mx = a8[0];
#pragma unroll
        for (int b = 1; b < 8; b++) mx = fmaxf(mx, a8[b]);
        mx = fmaxf(mx, __shfl_xor_sync(0xffffffffu, mx, 1));
        float ssum = 0.f;
#pragma unroll
        for (int b = 0; b < 8; b++) { a8[b] = __expf(a8[b] - mx); ssum += a8[b]; }
        ssum += __shfl_xor_sync(0xffffffffu, ssum, 1);
        float invs = 1.f / ssum;
#pragma unroll
        for (int b = 0; b < 8; b++) a8[b] *= invs;
        unsigned long long att2[4];
        att2[0] = pack2(a8[0], a8[1]);
        att2[1] = pack2(a8[2], a8[3]);
        att2[2] = pack2(a8[4], a8[5]);
        att2[3] = pack2(a8[6], a8[7]);

#pragma unroll
        for (int hh = 0; hh < 32; hh++) {
            ulonglong2 vA = Vs2[hh * 4 + half2];
            ulonglong2 vB = Vs2[hh * 4 + half2 + 1];
            fma2(partial2[hh], att2[0], vA.x);
            fma2(partial2[hh], att2[1], vA.y);
            fma2(partial2[hh], att2[2], vB.x);
            fma2(partial2[hh], att2[3], vB.y);
        }

        if (e + 1 < e1) {
            float4* kd = (float4*)&KVs[winb][cur ^ 1][0];
            float4* vd = kd + 128;
#pragma unroll
            for (int v = 0; v < 4; v++) { kd[lane + 32 * v] = kr[v]; vd[lane + 32 * v] = vr[v]; }
        }
        __syncwarp();
        cur ^= 1;
    }

    __half* oph = Omh + (size_t)i * QKV;
    __half* opl = Oml + (size_t)i * QKV;
#pragma unroll
    for (int h = 0; h < 32; h++) {
        float pe, po;
        unpack2(partial2[h], pe, po);
        float tot = pe + po;
        tot += __shfl_xor_sync(0xffffffffu, tot, 1);
        if ((h >> 4) == half) {
            int idx = h * 16 + a;
            __half th, tl;
            splith(tot, th, tl);
            oph[idx] = th;
            opl[idx] = tl;
        }
    }
}

// ---------------- host launcher ----------------
extern "C" void kernel_launch(void* const* d_in, const int* in_sizes, int n_in,
                              void* d_out, int out_size)
{
    const float* x       = (const float*)d_in[0];
    const void*  eidx    =               d_in[1];
    const float* W_embed = (const float*)d_in[2];
    const float* Wq      = (const float*)d_in[3];
    const float* Wk      = (const float*)d_in[4];
    const float* Wv      = (const float*)d_in[5];
    const float* Wo      = (const float*)d_in[6];
    const float* bo      = (const float*)d_in[7];
    const float* Wm      = (const float*)d_in[8];
    const float* bm      = (const float*)d_in[9];
    const float* g_ln    = (const float*)d_in[10];
    const float* b_ln    = (const float*)d_in[11];
    const float* g_mlp   = (const float*)d_in[12];
    const float* b_mlp   = (const float*)d_in[13];
    float* out = (float*)d_out;

    __half *pxh, *pxl, *pWeh, *pWel, *pWfh, *pWfl, *pWoh, *pWol, *pWmh, *pWml;
    __half *phh, *phl, *pt1h, *pt1l, *pAh, *pAl;
    float *ph, *pt0, *pt1, *pQKV;
    cudaGetSymbolAddress((void**)&pxh,  g_xh);
    cudaGetSymbolAddress((void**)&pxl,  g_xl);
    cudaGetSymbolAddress((void**)&pWeh, g_Weh);
    cudaGetSymbolAddress((void**)&pWel, g_Wel);
    cudaGetSymbolAddress((void**)&pWfh, g_Wfh);
    cudaGetSymbolAddress((void**)&pWfl, g_Wfl);
    cudaGetSymbolAddress((void**)&pWoh, g_Woh);
    cudaGetSymbolAddress((void**)&pWol, g_Wol);
    cudaGetSymbolAddress((void**)&pWmh, g_Wmh);
    cudaGetSymbolAddress((void**)&pWml, g_Wml);
    cudaGetSymbolAddress((void**)&ph,   g_h);
    cudaGetSymbolAddress((void**)&phh,  g_hh);
    cudaGetSymbolAddress((void**)&phl,  g_hl);
    cudaGetSymbolAddress((void**)&pt0,  g_t0);
    cudaGetSymbolAddress((void**)&pt1,  g_t1);
    cudaGetSymbolAddress((void**)&pt1h, g_t1h);
    cudaGetSymbolAddress((void**)&pt1l, g_t1l);
    cudaGetSymbolAddress((void**)&pQKV, g_QKV);
    cudaGetSymbolAddress((void**)&pAh,  g_ath);
    cudaGetSymbolAddress((void**)&pAl,  g_atl);

    cudaFuncSetAttribute(gemm3h, cudaFuncAttributeMaxDynamicSharedMemorySize,
                         GEMM_SMEM_BYTES);

    // launches 1-3: splits (x unscaled; all weights x32)
    split_pad_kernel<<<NNODE, 256>>>(x, pxh, pxl, FIN, KPAD, 1.0f);
    split_pad_kernel<<<DMODEL, 256>>>(W_embed, pWeh, pWel, FIN, KPAD, WSCALE);
    splitw_kernel<<<(WTOT + 255) / 256, 256>>>(Wq, Wk, Wv, Wo, Wm);

    // launch 4: embedding GEMM (profiler captures launch #4)
    const dim3 gEmb(DMODEL / BN, (NNODE + 127) / 128);   // 2 x 79
    gemm3h<<<gEmb, 256, GEMM_SMEM_BYTES>>>(pxh, pxl, pWeh, pWel, nullptr, nullptr,
                                           ph, phh, phl, NNODE, DMODEL, KPAD);

    // CSR build
    detect_kernel<<<1, 32>>>((const unsigned int*)eidx);
    zero_cnt_kernel<<<(NNODE + 255) / 256, 256>>>();
    hist_kernel<<<(NEDGE + 255) / 256, 256>>>(eidx);
    scan_kernel<<<1, 1024>>>();
    scatter_kernel<<<(NEDGE + 255) / 256, 256>>>(eidx);

    const dim3 gF(QKV3 / BN,   (NNODE + 127) / 128);     // 12 x 79
    const dim3 gD(DMODEL / BN, (NNODE + 127) / 128);     // 2 x 79

    for (int l = 0; l < NLAYER; l++) {
        // fused QKV
        gemm3h<<<gF, 256, GEMM_SMEM_BYTES>>>(phh, phl,
                                             pWfh + (size_t)l * QKV3 * DMODEL,
                                             pWfl + (size_t)l * QKV3 * DMODEL,
                                             nullptr, nullptr, pQKV, nullptr, nullptr,
                                             NNODE, QKV3, DMODEL);

        attn_kernel<<<(NNODE + 3) / 4, 128>>>(pQKV, pAh, pAl);

        // h1x = h + attn @ Wo^T + bo
        gemm3h<<<gD, 256, GEMM_SMEM_BYTES>>>(pAh, pAl,
                                             pWoh + (size_t)l * DMODEL * QKV,
                                             pWol + (size_t)l * DMODEL * QKV,
                                             bo + (size_t)l * DMODEL, ph,
                                             pt0, nullptr, nullptr,
                                             NNODE, DMODEL, QKV);
        ln_kernel<<<(NNODE * 32 + 255) / 256, 256>>>(pt0, g_ln + (size_t)l * DMODEL,
                                                     b_ln + (size_t)l * DMODEL,
                                                     pt1, pt1h, pt1l);

        // h2 = h1 + h1 @ Wm^T + bm
        gemm3h<<<gD, 256, GEMM_SMEM_BYTES>>>(pt1h, pt1l,
                                             pWmh + (size_t)l * DMODEL * DMODEL,
                                             pWml + (size_t)l * DMODEL * DMODEL,
                                             bm + (size_t)l * DMODEL, pt1,
                                             pt0, nullptr, nullptr,
                                             NNODE, DMODEL, DMODEL);
        bool last = (l == NLAYER - 1);
        ln_kernel<<<(NNODE * 32 + 255) / 256, 256>>>(pt0, g_mlp + (size_t)l * DMODEL,
                                                     b_mlp + (size_t)l * DMODEL,
                                                     last ? out : ph,
                                                     last ? nullptr : phh,
                                                     last ? nullptr : phl);
    }
}

// round 12
// speedup vs baseline: 1.0065x; 1.0065x over previous
#include <cuda_runtime.h>
#include <cuda_fp16.h>

// Problem constants
#define NNODE   10000
#define NEDGE   160000
#define FIN     3703
#define KPAD    3712     // FIN padded to multiple of 32 (split-K halves stay x16)
#define DMODEL  256
#define NHEAD   32
#define DK      16
#define QKV     512
#define QKV3    1536
#define NLAYER  7

// GEMM tiling (fp16 3-term, double buffer, R10-proven skeleton)
#define BM 128
#define BN 128
#define SROWH 24                   // 16 halves + 8 pad (48B rows, LDSM conflict-free)
#define TILE_H (128*SROWH)
#define STAGE_H (4*TILE_H)         // Ah | Al | Bh | Bl
#define WSCALE 32.0f
#define WINV   0.03125f

#define SQ1 (QKV*DMODEL)
#define SQT (NLAYER*SQ1)
#define SOT (NLAYER*DMODEL*QKV)
#define SMT (NLAYER*DMODEL*DMODEL)
#define WTOT (3*SQT + SOT + SMT)

// ---------------- device scratch ----------------
__device__ __half g_xh [NNODE * KPAD];
__device__ __half g_xl [NNODE * KPAD];
__device__ __half g_Weh[DMODEL * KPAD];
__device__ __half g_Wel[DMODEL * KPAD];
__device__ __half g_Wfh[NLAYER * QKV3 * DMODEL];
__device__ __half g_Wfl[NLAYER * QKV3 * DMODEL];
__device__ __half g_Woh[SOT];
__device__ __half g_Wol[SOT];
__device__ __half g_Wmh[SMT];
__device__ __half g_Wml[SMT];

__device__ float  g_h  [NNODE * DMODEL];
__device__ __half g_hh [NNODE * DMODEL];
__device__ __half g_hl [NNODE * DMODEL];
__device__ float  g_p0 [NNODE * DMODEL];   // split-K partial 0
__device__ float  g_p1 [NNODE * DMODEL];   // split-K partial 1
__device__ float  g_t1 [NNODE * DMODEL];
__device__ __half g_t1h[NNODE * DMODEL];
__device__ __half g_t1l[NNODE * DMODEL];
__device__ float  g_QKV[NNODE * QKV3];
__device__ __half g_ath[NNODE * QKV];
__device__ __half g_atl[NNODE * QKV];

__device__ int g_cnt [NNODE];
__device__ int g_off [NNODE + 1];
__device__ int g_cur [NNODE];
__device__ int g_esrc[NEDGE];
__device__ int g_is64;

// ---------------- fp16 two-term split ----------------
__device__ __forceinline__ void splith(float x, __half& hi, __half& lo) {
    hi = __float2half_rn(x);
    lo = __float2half_rn(x - __half2float(hi));
}

// ---------------- f32x2 packed helpers ----------------
__device__ __forceinline__ unsigned long long pack2(float lo, float hi) {
    unsigned long long r;
    asm("mov.b64 %0, {%1, %2};" : "=l"(r) : "f"(lo), "f"(hi));
    return r;
}
__device__ __forceinline__ void unpack2(unsigned long long v, float& lo, float& hi) {
    asm("mov.b64 {%0, %1}, %2;" : "=f"(lo), "=f"(hi) : "l"(v));
}
__device__ __forceinline__ void fma2(unsigned long long& d,
                                     unsigned long long a, unsigned long long b) {
    asm("fma.rn.f32x2 %0, %1, %2, %0;" : "+l"(d) : "l"(a), "l"(b));
}
__device__ __forceinline__ unsigned long long add2(unsigned long long a,
                                                   unsigned long long b) {
    unsigned long long r;
    asm("add.rn.f32x2 %0, %1, %2;" : "=l"(r) : "l"(a), "l"(b));
    return r;
}

// ---------------- split kernels ----------------
__global__ void split_pad_kernel(const float* __restrict__ src,
                                 __half* __restrict__ hi, __half* __restrict__ lo,
                                 int cols, int colspad, float scale) {
    int row = blockIdx.x;
    const float* s = src + (size_t)row * cols;
    __half* ph = hi + (size_t)row * colspad;
    __half* pl = lo + (size_t)row * colspad;
    for (int c = threadIdx.x; c < cols; c += blockDim.x) {
        __half h, l;
        splith(s[c] * scale, h, l);
        ph[c] = h; pl[c] = l;
    }
}

__global__ void splitw_kernel(const float* __restrict__ Wq, const float* __restrict__ Wk,
                              const float* __restrict__ Wv, const float* __restrict__ Wo,
                              const float* __restrict__ Wm) {
    int idx = blockIdx.x * blockDim.x + threadIdx.x;
    if (idx >= WTOT) return;
    float v; __half *dh, *dl;
    if (idx < SQT) {
        int l = idx / SQ1, r = idx % SQ1;
        v = Wq[idx]; int d = l * (3 * SQ1) + r;
        dh = g_Wfh + d; dl = g_Wfl + d;
    } else if (idx < 2 * SQT) {
        int i2 = idx - SQT;
        int l = i2 / SQ1, r = i2 % SQ1;
        v = Wk[i2]; int d = l * (3 * SQ1) + SQ1 + r;
        dh = g_Wfh + d; dl = g_Wfl + d;
    } else if (idx < 3 * SQT) {
        int i2 = idx - 2 * SQT;
        int l = i2 / SQ1, r = i2 % SQ1;
        v = Wv[i2]; int d = l * (3 * SQ1) + 2 * SQ1 + r;
        dh = g_Wfh + d; dl = g_Wfl + d;
    } else if (idx < 3 * SQT + SOT) {
        int i2 = idx - 3 * SQT;
        v = Wo[i2]; dh = g_Woh + i2; dl = g_Wol + i2;
    } else {
        int i2 = idx - 3 * SQT - SOT;
        v = Wm[i2]; dh = g_Wmh + i2; dl = g_Wml + i2;
    }
    __half h, l;
    splith(v * WSCALE, h, l);
    *dh = h; *dl = l;
}

// ---------------- edge index dtype detection + CSR ----------------
__global__ void detect_kernel(const unsigned int* __restrict__ w) {
    if (threadIdx.x == 0 && blockIdx.x == 0) {
        int is64 = 1;
        for (int i = 1; i < 128; i += 2)
            if (w[i] != 0u) { is64 = 0; break; }
        g_is64 = is64;
    }
}

__device__ __forceinline__ int read_edge(const void* eidx, int pos) {
    if (g_is64) return (int)(((const long long*)eidx)[pos]);
    return ((const int*)eidx)[pos];
}

__global__ void zero_cnt_kernel() {
    int i = blockIdx.x * blockDim.x + threadIdx.x;
    if (i < NNODE) g_cnt[i] = 0;
}

__global__ void hist_kernel(const void* __restrict__ eidx) {
    int e = blockIdx.x * blockDim.x + threadIdx.x;
    if (e >= NEDGE) return;
    atomicAdd(&g_cnt[read_edge(eidx, NEDGE + e)], 1);
}

__global__ void scan_kernel() {
    __shared__ int ss[1024];
    int t = threadIdx.x;
    const int CH = (NNODE + 1023) / 1024;
    int b = t * CH;
    int e = b + CH; if (e > NNODE) e = NNODE;
    int s = 0;
    for (int i = b; i < e; i++) s += g_cnt[i];
    ss[t] = s;
    __syncthreads();
    for (int o = 1; o < 1024; o <<= 1) {
        int v = (t >= o) ? ss[t - o] : 0;
        __syncthreads();
        ss[t] += v;
        __syncthreads();
    }
    int base = ss[t] - s;
    for (int i = b; i < e; i++) {
        g_off[i] = base;
        g_cur[i] = base;
        base += g_cnt[i];
    }
    if (t == 1023) g_off[NNODE] = ss[1023];
}

__global__ void scatter_kernel(const void* __restrict__ eidx) {
    int e = blockIdx.x * blockDim.x + threadIdx.x;
    if (e >= NEDGE) return;
    int d = read_edge(eidx, NEDGE + e);
    int s = read_edge(eidx, e);
    g_esrc[atomicAdd(&g_cur[d], 1)] = s;
}

// ---------------- fp16 mma + ldmatrix helpers ----------------
__device__ __forceinline__ void mma16(float* c,
                                      unsigned a0, unsigned a1, unsigned a2, unsigned a3,
                                      unsigned b0, unsigned b1) {
    asm volatile(
        "mma.sync.aligned.m16n8k16.row.col.f32.f16.f16.f32 "
        "{%0,%1,%2,%3}, {%4,%5,%6,%7}, {%8,%9}, {%0,%1,%2,%3};\n"
        : "+f"(c[0]), "+f"(c[1]), "+f"(c[2]), "+f"(c[3])
        : "r"(a0), "r"(a1), "r"(a2), "r"(a3), "r"(b0), "r"(b1));
}

__device__ __forceinline__ void ldsm4(unsigned& r0, unsigned& r1,
                                      unsigned& r2, unsigned& r3, unsigned addr) {
    asm volatile(
        "ldmatrix.sync.aligned.m8n8.x4.shared.b16 {%0,%1,%2,%3}, [%4];\n"
        : "=r"(r0), "=r"(r1), "=r"(r2), "=r"(r3) : "r"(addr));
}

// ---------------- GEMM: C(z) = (A @ B^T)/32 over K-slice z  (3xFP16) ------
// Row stride is Kstride; this launch processes Klen columns starting at
// z*Klen. Partials written raw (combine + bias + residual fused into LN).
__global__ __launch_bounds__(256, 2)
void gemm3h(const __half* __restrict__ Ah, const __half* __restrict__ Al,
            const __half* __restrict__ Bh, const __half* __restrict__ Bl,
            float* __restrict__ C0, float* __restrict__ C1,
            int M, int Nn, int Klen, int Kstride)
{
    __shared__ __align__(16) __half smem[2][STAGE_H];   // 48 KB

    const int tid = threadIdx.x;
    const int m0 = blockIdx.y * BM;
    const int n0 = blockIdx.x * BN;
    const int koff = blockIdx.z * Klen;
    float* __restrict__ C = blockIdx.z ? C1 : C0;
    const int lane = tid & 31, wid = tid >> 5;
    const int wm = wid & 1, wn = wid >> 1;

    const int nkt = Klen >> 4;

    float acc[4][4][4] = {};

    const int lr = tid >> 1;
    const int lc = (tid & 1) * 8;
    const int mA = (m0 + lr < M) ? (m0 + lr) : (M - 1);
    const int nB = n0 + lr;

    const int a_row = ((lane >> 3) & 1) * 8 + (lane & 7);
    const int a_col = ((lane >> 4) & 1) * 8;
    const unsigned aoffB = (unsigned)((a_row * SROWH + a_col) * 2);
    const int b_row = ((lane >> 4) & 1) * 8 + (lane & 7);
    const int b_col = ((lane >> 3) & 1) * 8;
    const unsigned boffB = (unsigned)((b_row * SROWH + b_col) * 2);

    unsigned sbase[2];
    sbase[0] = (unsigned)__cvta_generic_to_shared(&smem[0][0]);
    sbase[1] = (unsigned)__cvta_generic_to_shared(&smem[1][0]);

    uint4 vah, val, vbh, vbl;

#define LOADT(t_) do {                                                         \
        const int _k = koff + ((t_) << 4) + lc;                                \
        vah = *(const uint4*)(Ah + (size_t)mA * Kstride + _k);                 \
        val = *(const uint4*)(Al + (size_t)mA * Kstride + _k);                 \
        vbh = *(const uint4*)(Bh + (size_t)nB * Kstride + _k);                 \
        vbl = *(const uint4*)(Bl + (size_t)nB * Kstride + _k);                 \
    } while (0)

#define STORET(st_) do {                                                       \
        __half* _s = smem[st_];                                                \
        *(uint4*)&_s[             lr * SROWH + lc] = vah;                      \
        *(uint4*)&_s[TILE_H     + lr * SROWH + lc] = val;                      \
        *(uint4*)&_s[2 * TILE_H + lr * SROWH + lc] = vbh;                      \
        *(uint4*)&_s[3 * TILE_H + lr * SROWH + lc] = vbl;                      \
    } while (0)

    LOADT(0);
    STORET(0);
    __syncthreads();

    for (int t = 0; t < nkt; t++) {
        const int cur = t & 1;
        if (t + 1 < nkt) LOADT(t + 1);

        const unsigned sb = sbase[cur];

        unsigned bh0[4], bh1[4], bl0[4], bl1[4];
#pragma unroll
        for (int jp = 0; jp < 2; jp++) {
            unsigned bd = sb + (unsigned)((2 * TILE_H + (wn * 32 + jp * 16) * SROWH) * 2) + boffB;
            ldsm4(bh0[2 * jp], bh1[2 * jp], bh0[2 * jp + 1], bh1[2 * jp + 1], bd);
            ldsm4(bl0[2 * jp], bl1[2 * jp], bl0[2 * jp + 1], bl1[2 * jp + 1],
                  bd + (unsigned)(TILE_H * 2));
        }
#pragma unroll
        for (int i = 0; i < 4; i++) {
            unsigned ad = sb + (unsigned)(((wm * 64 + i * 16) * SROWH) * 2) + aoffB;
            unsigned ah0, ah1, ah2, ah3, al0, al1, al2, al3;
            ldsm4(ah0, ah1, ah2, ah3, ad);
            ldsm4(al0, al1, al2, al3, ad + (unsigned)(TILE_H * 2));
#pragma unroll
            for (int j = 0; j < 4; j++) {
                mma16(acc[i][j], ah0, ah1, ah2, ah3, bh0[j], bh1[j]);
                mma16(acc[i][j], al0, al1, al2, al3, bh0[j], bh1[j]);
                mma16(acc[i][j], ah0, ah1, ah2, ah3, bl0[j], bl1[j]);
            }
        }

        if (t + 1 < nkt) STORET(cur ^ 1);
        __syncthreads();
    }
#undef LOADT
#undef STORET

    // epilogue: raw partials, rescale by 1/32
#pragma unroll
    for (int i = 0; i < 4; i++) {
        int mrow = m0 + wm * 64 + i * 16 + (lane >> 2);
#pragma unroll
        for (int j = 0; j < 4; j++) {
            int ncol = n0 + wn * 32 + j * 8 + (lane & 3) * 2;
#pragma unroll
            for (int r = 0; r < 2; r++) {
                int mr = mrow + r * 8;
                if (mr >= M) continue;
                size_t idx = (size_t)mr * Nn + ncol;
                C[idx]     = acc[i][j][r * 2 + 0] * WINV;
                C[idx + 1] = acc[i][j][r * 2 + 1] * WINV;
            }
        }
    }
}

// ---------------- add + split (embed combine) ----------------
__global__ void addsplit_kernel(const float* __restrict__ X0,
                                const float* __restrict__ X1,
                                float* __restrict__ Y,
                                __half* __restrict__ Yh, __half* __restrict__ Yl)
{
    int idx = blockIdx.x * blockDim.x + threadIdx.x;   // float4 index
    if (idx >= NNODE * DMODEL / 4) return;
    float4 a = ((const float4*)X0)[idx];
    float4 b = ((const float4*)X1)[idx];
    float4 v = make_float4(a.x + b.x, a.y + b.y, a.z + b.z, a.w + b.w);
    ((float4*)Y)[idx] = v;
    __half hb[4], lb[4];
    splith(v.x, hb[0], lb[0]); splith(v.y, hb[1], lb[1]);
    splith(v.z, hb[2], lb[2]); splith(v.w, hb[3], lb[3]);
    ((uint2*)Yh)[idx] = *(uint2*)hb;
    ((uint2*)Yl)[idx] = *(uint2*)lb;
}

// ---------------- LayerNorm: x = X0 + X1 + bias + addend, then LN ---------
__global__ __launch_bounds__(256)
void ln_kernel(const float* __restrict__ X0, const float* __restrict__ X1,
               const float* __restrict__ bias, const float* __restrict__ addend,
               const float* __restrict__ gamma, const float* __restrict__ beta,
               float* __restrict__ Y, __half* __restrict__ Yh, __half* __restrict__ Yl)
{
    int idx = blockIdx.x * blockDim.x + threadIdx.x;
    int row = idx >> 5;
    int lane = idx & 31;
    if (row >= NNODE) return;

    const float4* xp = (const float4*)(X0 + (size_t)row * DMODEL);
    float4 v0 = xp[lane];
    float4 v1 = xp[lane + 32];
    {
        const float4* x1 = (const float4*)(X1 + (size_t)row * DMODEL);
        float4 u0 = x1[lane], u1 = x1[lane + 32];
        v0.x += u0.x; v0.y += u0.y; v0.z += u0.z; v0.w += u0.w;
        v1.x += u1.x; v1.y += u1.y; v1.z += u1.z; v1.w += u1.w;
    }
    {
        const float4* bp = (const float4*)bias;
        float4 u0 = bp[lane], u1 = bp[lane + 32];
        v0.x += u0.x; v0.y += u0.y; v0.z += u0.z; v0.w += u0.w;
        v1.x += u1.x; v1.y += u1.y; v1.z += u1.z; v1.w += u1.w;
    }
    {
        const float4* ap = (const float4*)(addend + (size_t)row * DMODEL);
        float4 u0 = ap[lane], u1 = ap[lane + 32];
        v0.x += u0.x; v0.y += u0.y; v0.z += u0.z; v0.w += u0.w;
        v1.x += u1.x; v1.y += u1.y; v1.z += u1.z; v1.w += u1.w;
    }

    float s = v0.x + v0.y + v0.z + v0.w + v1.x + v1.y + v1.z + v1.w;
#pragma unroll
    for (int o = 16; o; o >>= 1) s += __shfl_xor_sync(0xffffffffu, s, o);
    float mean = s * (1.f / 256.f);

    float d, q = 0.f;
    d = v0.x - mean; q += d * d;  d = v0.y - mean; q += d * d;
    d = v0.z - mean; q += d * d;  d = v0.w - mean; q += d * d;
    d = v1.x - mean; q += d * d;  d = v1.y - mean; q += d * d;
    d = v1.z - mean; q += d * d;  d = v1.w - mean; q += d * d;
#pragma unroll
    for (int o = 16; o; o >>= 1) q += __shfl_xor_sync(0xffffffffu, q, o);
    float inv = rsqrtf(q * (1.f / 256.f) + 1e-5f);

    const float4* gp = (const float4*)gamma;
    const float4* bp = (const float4*)beta;
    float4 g0 = gp[lane], g1 = gp[lane + 32];
    float4 b0 = bp[lane], b1 = bp[lane + 32];

    float o0[4], o1[4];
    o0[0] = (v0.x - mean) * inv * g0.x + b0.x;
    o0[1] = (v0.y - mean) * inv * g0.y + b0.y;
    o0[2] = (v0.z - mean) * inv * g0.z + b0.z;
    o0[3] = (v0.w - mean) * inv * g0.w + b0.w;
    o1[0] = (v1.x - mean) * inv * g1.x + b1.x;
    o1[1] = (v1.y - mean) * inv * g1.y + b1.y;
    o1[2] = (v1.z - mean) * inv * g1.z + b1.z;
    o1[3] = (v1.w - mean) * inv * g1.w + b1.w;

    float4* yp = (float4*)(Y + (size_t)row * DMODEL);
    yp[lane]      = make_float4(o0[0], o0[1], o0[2], o0[3]);
    yp[lane + 32] = make_float4(o1[0], o1[1], o1[2], o1[3]);

    if (Yh) {
        __half hbuf0[4], lbuf0[4], hbuf1[4], lbuf1[4];
#pragma unroll
        for (int k = 0; k < 4; k++) {
            splith(o0[k], hbuf0[k], lbuf0[k]);
            splith(o1[k], hbuf1[k], lbuf1[k]);
        }
        uint2* hp = (uint2*)(Yh + (size_t)row * DMODEL);
        uint2* lp = (uint2*)(Yl + (size_t)row * DMODEL);
        hp[lane]      = *(uint2*)hbuf0;
        hp[lane + 32] = *(uint2*)hbuf1;
        lp[lane]      = *(uint2*)lbuf0;
        lp[lane + 32] = *(uint2*)lbuf1;
    }
}

// ---------------- edge attention: warp/node, f32x2, Q packed in smem -----
__global__ __launch_bounds__(128)
void attn_kernel(const float* __restrict__ QKVm,
                 __half* __restrict__ Omh, __half* __restrict__ Oml)
{
    __shared__ unsigned long long Qd[4][512];
    __shared__ float KVs[4][2][1024];

    const int gwarp = (blockIdx.x * blockDim.x + threadIdx.x) >> 5;
    const int lane  = threadIdx.x & 31;
    const int winb  = threadIdx.x >> 5;
    if (gwarp >= NNODE) return;

    const int i = gwarp;
    const int a = lane >> 1;
    const int half = lane & 1;
    const int half2 = half * 2;

    {
        const float4* qg = (const float4*)(QKVm + (size_t)i * QKV3);
#pragma unroll
        for (int v = 0; v < 4; v++) {
            float4 q = qg[lane + 32 * v];
            int e = (lane + 32 * v) * 4;
            ulonglong2* d = (ulonglong2*)&Qd[winb][e];
            float x0 = q.x * 0.25f, x1 = q.y * 0.25f;
            float x2 = q.z * 0.25f, x3 = q.w * 0.25f;
            d[0] = make_ulonglong2(pack2(x0, x0), pack2(x1, x1));
            d[1] = make_ulonglong2(pack2(x2, x2), pack2(x3, x3));
        }
    }

    unsigned long long partial2[32];
#pragma unroll
    for (int h = 0; h < 32; h++) partial2[h] = 0ull;

    const int e0 = g_off[i];
    const int e1 = g_off[i + 1];

    float4 kr[4], vr[4];
    if (e0 < e1) {
        const float4* kg = (const float4*)(QKVm + (size_t)g_esrc[e0] * QKV3 + QKV);
        const float4* vg = kg + 128;
#pragma unroll
        for (int v = 0; v < 4; v++) { kr[v] = kg[lane + 32 * v]; vr[v] = vg[lane + 32 * v]; }
        float4* kd = (float4*)&KVs[winb][0][0];
        float4* vd = kd + 128;
#pragma unroll
        for (int v = 0; v < 4; v++) { kd[lane + 32 * v] = kr[v]; vd[lane + 32 * v] = vr[v]; }
    }
    __syncwarp();

    int cur = 0;
    for (int e = e0; e < e1; e++) {
        if (e + 1 < e1) {
            const float4* kg = (const float4*)(QKVm + (size_t)g_esrc[e + 1] * QKV3 + QKV);
            const float4* vg = kg + 128;
#pragma unroll
            for (int v = 0; v < 4; v++) { kr[v] = kg[lane + 32 * v]; vr[v] = vg[lane + 32 * v]; }
        }

        const ulonglong2* Ks2 = (const ulonglong2*)&KVs[winb][cur][0];
        const ulonglong2* Vs2 = Ks2 + 128;

        unsigned long long acc2[8] = {0ull,0ull,0ull,0ull,0ull,0ull,0ull,0ull};
#pragma unroll
        for (int hh = 0; hh < 32; hh += 2) {
            unsigned long long q0 = Qd[winb][hh * 16 + a];
            unsigned long long q1 = Qd[winb][(hh + 1) * 16 + a];
            ulonglong2 kA0 = Ks2[hh * 4 + half2];
            ulonglong2 kB0 = Ks2[hh * 4 + half2 + 1];
            ulonglong2 kA1 = Ks2[(hh + 1) * 4 + half2];
            ulonglong2 kB1 = Ks2[(hh + 1) * 4 + half2 + 1];
            fma2(acc2[0], q0, kA0.x); fma2(acc2[1], q0, kA0.y);
            fma2(acc2[2], q0, kB0.x); fma2(acc2[3], q0, kB0.y);
            fma2(acc2[4], q1, kA1.x); fma2(acc2[5], q1, kA1.y);
            fma2(acc2[6], q1, kB1.x); fma2(acc2[7], q1, kB1.y);
        }
        acc2[0] = add2(acc2[0], acc2[4]);
        acc2[1] = add2(acc2[1], acc2[5]);
        acc2[2] = add2(acc2[2], acc2[6]);
        acc2[3] = add2(acc2[3], acc2[7]);

        float a8[8];
        unpack2(acc2[0], a8[0], a8[1]);
        unpack2(acc2[1], a8[2], a8[3]);
        unpack2(acc2[2], a8[4], a8[5]);
        unpack2(acc2[3], a8[6], a8[7]);
        float mx = a8[0];
#pragma unroll
        for (int b = 1; b < 8; b++) mx = fmaxf(mx, a8[b]);
        mx = fmaxf(mx, __shfl_xor_sync(0xffffffffu, mx, 1));
        float ssum = 0.f;
#pragma unroll
        for (int b = 0; b < 8; b++) { a8[b] = __expf(a8[b] - mx); ssum += a8[b]; }
        ssum += __shfl_xor_sync(0xffffffffu, ssum, 1);
        float invs = 1.f / ssum;
#pragma unroll
        for (int b = 0; b < 8; b++) a8[b] *= invs;
        unsigned long long att2[4];
        att2[0] = pack2(a8[0], a8[1]);
        att2[1] = pack2(a8[2], a8[3]);
        att2[2] = pack2(a8[4], a8[5]);
        att2[3] = pack2(a8[6], a8[7]);

#pragma unroll
        for (int hh = 0; hh < 32; hh++) {
            ulonglong2 vA = Vs2[hh * 4 + half2];
            ulonglong2 vB = Vs2[hh * 4 + half2 + 1];
            fma2(partial2[hh], att2[0], vA.x);
            fma2(partial2[hh], att2[1], vA.y);
            fma2(partial2[hh], att2[2], vB.x);
            fma2(partial2[hh], att2[3], vB.y);
        }

        if (e + 1 < e1) {
            float4* kd = (float4*)&KVs[winb][cur ^ 1][0];
            float4* vd = kd + 128;
#pragma unroll
            for (int v = 0; v < 4; v++) { kd[lane + 32 * v] = kr[v]; vd[lane + 32 * v] = vr[v]; }
        }
        __syncwarp();
        cur ^= 1;
    }

    __half* oph = Omh + (size_t)i * QKV;
    __half* opl = Oml + (size_t)i * QKV;
#pragma unroll
    for (int h = 0; h < 32; h++) {
        float pe, po;
        unpack2(partial2[h], pe, po);
        float tot = pe + po;
        tot += __shfl_xor_sync(0xffffffffu, tot, 1);
        if ((h >> 4) == half) {
            int idx = h * 16 + a;
            __half th, tl;
            splith(tot, th, tl);
            oph[idx] = th;
            opl[idx] = tl;
        }
    }
}

// ---------------- host launcher ----------------
extern "C" void kernel_launch(void* const* d_in, const int* in_sizes, int n_in,
                              void* d_out, int out_size)
{
    const float* x       = (const float*)d_in[0];
    const void*  eidx    =               d_in[1];
    const float* W_embed = (const float*)d_in[2];
    const float* Wq      = (const float*)d_in[3];
    const float* Wk      = (const float*)d_in[4];
    const float* Wv      = (const float*)d_in[5];
    const float* Wo      = (const float*)d_in[6];
    const float* bo      = (const float*)d_in[7];
    const float* Wm      = (const float*)d_in[8];
    const float* bm      = (const float*)d_in[9];
    const float* g_ln    = (const float*)d_in[10];
    const float* b_ln    = (const float*)d_in[11];
    const float* g_mlp   = (const float*)d_in[12];
    const float* b_mlp   = (const float*)d_in[13];
    float* out = (float*)d_out;

    __half *pxh, *pxl, *pWeh, *pWel, *pWfh, *pWfl, *pWoh, *pWol, *pWmh, *pWml;
    __half *phh, *phl, *pt1h, *pt1l, *pAh, *pAl;
    float *ph, *pp0, *pp1, *pt1, *pQKV;
    cudaGetSymbolAddress((void**)&pxh,  g_xh);
    cudaGetSymbolAddress((void**)&pxl,  g_xl);
    cudaGetSymbolAddress((void**)&pWeh, g_Weh);
    cudaGetSymbolAddress((void**)&pWel, g_Wel);
    cudaGetSymbolAddress((void**)&pWfh, g_Wfh);
    cudaGetSymbolAddress((void**)&pWfl, g_Wfl);
    cudaGetSymbolAddress((void**)&pWoh, g_Woh);
    cudaGetSymbolAddress((void**)&pWol, g_Wol);
    cudaGetSymbolAddress((void**)&pWmh, g_Wmh);
    cudaGetSymbolAddress((void**)&pWml, g_Wml);
    cudaGetSymbolAddress((void**)&ph,   g_h);
    cudaGetSymbolAddress((void**)&phh,  g_hh);
    cudaGetSymbolAddress((void**)&phl,  g_hl);
    cudaGetSymbolAddress((void**)&pp0,  g_p0);
    cudaGetSymbolAddress((void**)&pp1,  g_p1);
    cudaGetSymbolAddress((void**)&pt1,  g_t1);
    cudaGetSymbolAddress((void**)&pt1h, g_t1h);
    cudaGetSymbolAddress((void**)&pt1l, g_t1l);
    cudaGetSymbolAddress((void**)&pQKV, g_QKV);
    cudaGetSymbolAddress((void**)&pAh,  g_ath);
    cudaGetSymbolAddress((void**)&pAl,  g_atl);

    // launches 1-3: splits (x unscaled; all weights x32)
    split_pad_kernel<<<NNODE, 256>>>(x, pxh, pxl, FIN, KPAD, 1.0f);
    split_pad_kernel<<<DMODEL, 256>>>(W_embed, pWeh, pWel, FIN, KPAD, WSCALE);
    splitw_kernel<<<(WTOT + 255) / 256, 256>>>(Wq, Wk, Wv, Wo, Wm);

    // launch 4: embedding GEMM, split-K z=2 (profiler captures launch #4)
    const dim3 gEmb(DMODEL / BN, (NNODE + 127) / 128, 2);   // 2 x 79 x 2
    gemm3h<<<gEmb, 256>>>(pxh, pxl, pWeh, pWel, pp0, pp1,
                          NNODE, DMODEL, KPAD / 2, KPAD);
    addsplit_kernel<<<(NNODE * DMODEL / 4 + 255) / 256, 256>>>(pp0, pp1,
                                                               ph, phh, phl);

    // CSR build
    detect_kernel<<<1, 32>>>((const unsigned int*)eidx);
    zero_cnt_kernel<<<(NNODE + 255) / 256, 256>>>();
    hist_kernel<<<(NEDGE + 255) / 256, 256>>>(eidx);
    scan_kernel<<<1, 1024>>>();
    scatter_kernel<<<(NEDGE + 255) / 256, 256>>>(eidx);

    const dim3 gF(QKV3 / BN,   (NNODE + 127) / 128, 1);     // 12 x 79
    const dim3 gD(DMODEL / BN, (NNODE + 127) / 128, 2);     // 2 x 79 x 2

    for (int l = 0; l < NLAYER; l++) {
        // fused QKV (single-K; grid already large)
        gemm3h<<<gF, 256>>>(phh, phl,
                            pWfh + (size_t)l * QKV3 * DMODEL,
                            pWfl + (size_t)l * QKV3 * DMODEL,
                            pQKV, nullptr, NNODE, QKV3, DMODEL, DMODEL);

        attn_kernel<<<(NNODE + 3) / 4, 128>>>(pQKV, pAh, pAl);

        // Wo split-K: partials -> p0,p1 ; LN fuses combine + bo + residual h
        gemm3h<<<gD, 256>>>(pAh, pAl,
                            pWoh + (size_t)l * DMODEL * QKV,
                            pWol + (size_t)l * DMODEL * QKV,
                            pp0, pp1, NNODE, DMODEL, QKV / 2, QKV);
        ln_kernel<<<(NNODE * 32 + 255) / 256, 256>>>(pp0, pp1,
                                                     bo + (size_t)l * DMODEL, ph,
                                                     g_ln + (size_t)l * DMODEL,
                                                     b_ln + (size_t)l * DMODEL,
                                                     pt1, pt1h, pt1l);

        // Wm split-K: partials -> p0,p1 ; LN fuses combine + bm + residual t1
        gemm3h<<<gD, 256>>>(pt1h, pt1l,
                            pWmh + (size_t)l * DMODEL * DMODEL,
                            pWml + (size_t)l * DMODEL * DMODEL,
                            pp0, pp1, NNODE, DMODEL, DMODEL / 2, DMODEL);
        bool last = (l == NLAYER - 1);
        ln_kernel<<<(NNODE * 32 + 255) / 256, 256>>>(pp0, pp1,
                                                     bm + (size_t)l * DMODEL, pt1,
                                                     g_mlp + (size_t)l * DMODEL,
                                                     b_mlp + (size_t)l * DMODEL,
                                                     last ? out : ph,
                                                     last ? nullptr : phh,
                                                     last ? nullptr : phl);
    }
}